// round 16
// baseline (speedup 1.0000x reference)
#include <cuda_runtime.h>
#include <math.h>

#define N     1024
#define NN    (N*N)
#define NB    32
#define NSTEP 32
#define BATCH 16

// ---------------- device scratch (no allocations allowed) ----------------
__device__ float g_lu[(size_t)BATCH * NN];     // 64 MB destructible LU workspace
__device__ float g_logdet[BATCH];
__device__ float g_swaptmp[(size_t)BATCH * 64 * N];  // row-gather staging (4 MB)
__device__ int   g_nal[NSTEP * BATCH];         // per-step # affected rows
__device__ int   g_aff[NSTEP * BATCH * 64];    // per-step affected dst rows (rel)
__device__ int   g_srcof[NSTEP * BATCH * 64];  // per-step src rows (rel)
__device__ int   g_cnt[4 * NSTEP * BATCH];     // completion counters: gn, gf, sn, sf

struct Hdr {
    int   active;
    int   idx[8];
    float weff[10];
    float beff;
};
__device__ Hdr g_hdr;

#define CNT(role, k, m) g_cnt[((role) * NSTEP + (k)) * BATCH + (m)]

// ---------------- stage A: copy x -> LU workspace, zero logdets + counters ----
__global__ void copy_kernel(const float* __restrict__ x) {
    size_t i = (size_t)blockIdx.x * blockDim.x + threadIdx.x;
    const float4* src = (const float4*)x;
    float4* dst = (float4*)g_lu;
    if (i < (size_t)BATCH * NN / 4) dst[i] = src[i];
    if (i < BATCH) g_logdet[i] = 0.0f;
    if (i < 4 * NSTEP * BATCH) g_cnt[i] = 0;
}

// ---------------- fused step kernel: swap roles + panel + rest in ONE launch ----
// Shared-memory union across roles.
union SmemU {
    struct {
        unsigned long long rvi[16];
        float s_piv[NB];
        float s_U[NB][NB + 1];       // also reused for U12n during narrow phase
        float Dp[NB][NB + 1];        // prev diag block for narrow phase
        float s_abs[NB];
        int   s_src[N];
        int   s_na;
    } p;
    struct {
        float D[NB][NB + 1];
        float sL[128][NB + 1];
        float sU[NB][132];
    } r;
};

__device__ __forceinline__ void spin_ge(int role, int k, int m, int target) {
    if (threadIdx.x == 0) {
        volatile int* p = &CNT(role, k, m);
        while (*p < target) __nanosleep(32);
    }
    __threadfence();
    __syncthreads();
}

__device__ __forceinline__ void mark_done(int role, int k, int m) {
    __syncthreads();
    __threadfence();
    if (threadIdx.x == 0) atomicAdd(&CNT(role, k, m), 1);
}

// gather narrow: cols [kbp1, kbp1+32) of all affected rows -> tmp[i][0..32)
__device__ void gatherN_role(int kr, int m) {
    int na = g_nal[kr * BATCH + m];
    int kb = kr * NB, kbp1 = kb + NB;
    const float* A = g_lu + (size_t)m * NN;
    float* tmp = g_swaptmp + (size_t)m * 64 * N;
    const int* srcl = g_srcof + (kr * BATCH + m) * 64;
    for (int idx = threadIdx.x; idx < na * NB; idx += 512) {
        int i = idx >> 5, c = idx & 31;
        tmp[i * N + c] = A[(size_t)(kb + srcl[i]) * N + kbp1 + c];
    }
    mark_done(0, kr, m);
}

// gather full: cols [kbp1+32, N) of row chunk -> tmp[i][32..32+WF)
__device__ void gatherF_role(int kr, int m, int chunk) {
    int na = g_nal[kr * BATCH + m];
    int kb = kr * NB, kbp1 = kb + NB;
    int WF = N - kbp1 - NB;
    const float* A = g_lu + (size_t)m * NN;
    float* tmp = g_swaptmp + (size_t)m * 64 * N;
    const int* srcl = g_srcof + (kr * BATCH + m) * 64;
    int lo = chunk * 8, hi = min(na, lo + 8);
    for (int i = lo; i < hi; i++) {
        const float4* s = (const float4*)(A + (size_t)(kb + srcl[i]) * N + kbp1 + NB);
        float4* d = (float4*)(tmp + (size_t)i * N + NB);
        for (int c = threadIdx.x; c < (WF >> 2); c += 512) d[c] = s[c];
    }
    mark_done(1, kr, m);
}

__device__ void scatterN_role(int kr, int m) {
    spin_ge(0, kr, m, 1);
    int na = g_nal[kr * BATCH + m];
    int kb = kr * NB, kbp1 = kb + NB;
    float* A = g_lu + (size_t)m * NN;
    const float* tmp = g_swaptmp + (size_t)m * 64 * N;
    const int* affl = g_aff + (kr * BATCH + m) * 64;
    for (int idx = threadIdx.x; idx < na * NB; idx += 512) {
        int i = idx >> 5, c = idx & 31;
        A[(size_t)(kb + affl[i]) * N + kbp1 + c] = tmp[i * N + c];
    }
    mark_done(2, kr, m);
}

__device__ void scatterF_role(int kr, int m, int chunk) {
    spin_ge(1, kr, m, 8);
    int na = g_nal[kr * BATCH + m];
    int kb = kr * NB, kbp1 = kb + NB;
    int WF = N - kbp1 - NB;
    float* A = g_lu + (size_t)m * NN;
    const float* tmp = g_swaptmp + (size_t)m * 64 * N;
    const int* affl = g_aff + (kr * BATCH + m) * 64;
    int lo = chunk * 8, hi = min(na, lo + 8);
    for (int i = lo; i < hi; i++) {
        const float4* s = (const float4*)(tmp + (size_t)i * N + NB);
        float4* d = (float4*)(A + (size_t)(kb + affl[i]) * N + kbp1 + NB);
        for (int c = threadIdx.x; c < (WF >> 2); c += 512) d[c] = s[c];
    }
    mark_done(3, kr, m);
}

// panel role: (optional) folded narrow update + register shift-array pivoted
// factorization (validated R6/R11 math). Dumps swap list for step kp.
__device__ void panel_role(SmemU* sm, int kp, int kr, int m) {
    float* A = g_lu + (size_t)m * NN;
    int kb = kp * NB;
    int R  = N - kb;
    int tid = threadIdx.x;
    int lane = tid & 31, wrp = tid >> 5;

    if (kr >= 0) spin_ge(2, kr, m, 1);   // narrow cols of this panel scattered

    int relA = tid, relB = tid + 512;
    bool actA = relA < R, actB = relB < R;
    int myA = relA, myB = relB;
    int exA = -1, exB = -1;

    float ca[NB], cb[NB];
    {
        const float4* pa = (const float4*)(A + (size_t)(kb + relA) * N + kb);
        const float4* pb = (const float4*)(A + (size_t)(kb + relB) * N + kb);
        #pragma unroll
        for (int q = 0; q < 8; q++) {
            float4 v = actA ? pa[q] : make_float4(0.f, 0.f, 0.f, 0.f);
            ca[4*q+0] = v.x; ca[4*q+1] = v.y; ca[4*q+2] = v.z; ca[4*q+3] = v.w;
            float4 w = actB ? pb[q] : make_float4(0.f, 0.f, 0.f, 0.f);
            cb[4*q+0] = w.x; cb[4*q+1] = w.y; cb[4*q+2] = w.z; cb[4*q+3] = w.w;
        }
    }
    if (tid == 0) sm->p.s_na = 0;

    // ---- folded narrow update (R4-validated structure) ----
    if (kp > 0) {
        int kbp = kb - NB;
        for (int i = tid; i < NB * NB; i += 512)
            sm->p.Dp[i / NB][i % NB] = A[(size_t)(kbp + i / NB) * N + kbp + (i % NB)];
        __syncthreads();
        if (tid < NB) {
            float v[NB];
            #pragma unroll
            for (int i = 0; i < NB; i++) v[i] = A[(size_t)(kbp + i) * N + kb + tid];
            #pragma unroll 1
            for (int j = 0; j < NB; j++) {
                float vj = v[j];
                #pragma unroll
                for (int i = 0; i < NB; i++)
                    if (i > j) v[i] -= sm->p.Dp[i][j] * vj;
            }
            #pragma unroll
            for (int i = 0; i < NB; i++) sm->p.s_U[i][tid] = v[i];
        }
        __syncthreads();
        if (actA) {
            const float4* lr = (const float4*)(A + (size_t)(kb + relA) * N + kbp);
            #pragma unroll
            for (int q = 0; q < 8; q++) {
                float4 l4 = lr[q];
                float lj0 = l4.x, lj1 = l4.y, lj2 = l4.z, lj3 = l4.w;
                #pragma unroll
                for (int t = 0; t < NB; t++) {
                    ca[t] -= lj0 * sm->p.s_U[4*q+0][t];
                    ca[t] -= lj1 * sm->p.s_U[4*q+1][t];
                    ca[t] -= lj2 * sm->p.s_U[4*q+2][t];
                    ca[t] -= lj3 * sm->p.s_U[4*q+3][t];
                }
            }
        }
        if (actB) {
            const float4* lr = (const float4*)(A + (size_t)(kb + relB) * N + kbp);
            #pragma unroll
            for (int q = 0; q < 8; q++) {
                float4 l4 = lr[q];
                float lj0 = l4.x, lj1 = l4.y, lj2 = l4.z, lj3 = l4.w;
                #pragma unroll
                for (int t = 0; t < NB; t++) {
                    cb[t] -= lj0 * sm->p.s_U[4*q+0][t];
                    cb[t] -= lj1 * sm->p.s_U[4*q+1][t];
                    cb[t] -= lj2 * sm->p.s_U[4*q+2][t];
                    cb[t] -= lj3 * sm->p.s_U[4*q+3][t];
                }
            }
        }
        __syncthreads();   // s_U reused by factor loop below
    }

    // ---- pivoted shift-array factorization ----
    #pragma unroll 1
    for (int j = 0; j < NB; j++) {
        unsigned long long key = 0ull;
        if (actA)
            key = ((unsigned long long)__float_as_uint(fabsf(ca[0])) << 32)
                | (unsigned long long)(0xFFFFFFFFu - (unsigned)myA);
        if (actB) {
            unsigned long long k2 =
                  ((unsigned long long)__float_as_uint(fabsf(cb[0])) << 32)
                | (unsigned long long)(0xFFFFFFFFu - (unsigned)myB);
            if (k2 > key) key = k2;
        }
        #pragma unroll
        for (int o = 16; o > 0; o >>= 1) {
            unsigned long long ok = __shfl_down_sync(0xffffffffu, key, o);
            if (ok > key) key = ok;
        }
        if (lane == 0) sm->p.rvi[wrp] = key;
        __syncthreads();

        unsigned long long bk = sm->p.rvi[0];
        #pragma unroll
        for (int w = 1; w < 16; w++) if (sm->p.rvi[w] > bk) bk = sm->p.rvi[w];
        int p = (int)(0xFFFFFFFFu - (unsigned)(bk & 0xFFFFFFFFull));
        if (tid == 0) sm->p.s_abs[j] = __uint_as_float((unsigned)(bk >> 32));

        if (actA) {
            if (myA == p) {
                #pragma unroll
                for (int t = 0; t < NB; t++) {
                    float v = ca[t];
                    int col = (t <= NB - 1 - j) ? (j + t) : (t - (NB - j));
                    sm->p.s_U[j][col] = v;
                    sm->p.s_piv[t] = (t <= NB - 1 - j) ? v : 0.0f;
                }
                actA = false; exA = j;
            } else if (myA == j) myA = p;
        }
        if (actB) {
            if (myB == p) {
                #pragma unroll
                for (int t = 0; t < NB; t++) {
                    float v = cb[t];
                    int col = (t <= NB - 1 - j) ? (j + t) : (t - (NB - j));
                    sm->p.s_U[j][col] = v;
                    sm->p.s_piv[t] = (t <= NB - 1 - j) ? v : 0.0f;
                }
                actB = false; exB = j;
            } else if (myB == j) myB = p;
        }
        __syncthreads();

        float inv = 1.0f / sm->p.s_piv[0];
        if (actA) {
            float lv = ca[0] * inv;
            #pragma unroll
            for (int t = 1; t < NB; t++) ca[t-1] = ca[t] - lv * sm->p.s_piv[t];
            ca[NB-1] = lv;
        }
        if (actB) {
            float lv = cb[0] * inv;
            #pragma unroll
            for (int t = 1; t < NB; t++) cb[t-1] = cb[t] - lv * sm->p.s_piv[t];
            cb[NB-1] = lv;
        }
    }
    __syncthreads();

    for (int i = tid; i < NB * NB; i += 512)
        A[(size_t)(kb + i / NB) * N + kb + (i % NB)] = sm->p.s_U[i / NB][i % NB];

    if (actA) {
        float4* pw = (float4*)(A + (size_t)(kb + myA) * N + kb);
        #pragma unroll
        for (int q = 0; q < 8; q++)
            pw[q] = make_float4(ca[4*q+0], ca[4*q+1], ca[4*q+2], ca[4*q+3]);
    }
    if (actB) {
        float4* pw = (float4*)(A + (size_t)(kb + myB) * N + kb);
        #pragma unroll
        for (int q = 0; q < 8; q++)
            pw[q] = make_float4(cb[4*q+0], cb[4*q+1], cb[4*q+2], cb[4*q+3]);
    }

    if (tid < 32) {
        float lg = logf(fmaxf(sm->p.s_abs[tid], 1e-45f));
        #pragma unroll
        for (int o = 16; o > 0; o >>= 1) lg += __shfl_down_sync(0xffffffffu, lg, o);
        if (tid == 0) g_logdet[m] += lg;
    }

    if (relA < R) {
        if (exA >= 0) sm->p.s_src[exA] = relA; else sm->p.s_src[myA] = relA;
    }
    if (relB < R) {
        if (exB >= 0) sm->p.s_src[exB] = relB; else sm->p.s_src[myB] = relB;
    }
    __syncthreads();
    for (int r = tid; r < R; r += 512) {
        if (sm->p.s_src[r] != r) {
            int i = atomicAdd(&sm->p.s_na, 1);
            g_aff[(kp * BATCH + m) * 64 + i] = r;
            g_srcof[(kp * BATCH + m) * 64 + i] = sm->p.s_src[r];
        }
    }
    __syncthreads();
    if (tid == 0) g_nal[kp * BATCH + m] = sm->p.s_na;
}

// rest role: local-TRSM + trailing update on cols [kb+64, N), 128x128 tile,
// 512 threads, 4x8 per thread (validated R11 math).
__device__ void rest_role(SmemU* sm, int k, int m, int t, int nx) {
    spin_ge(3, k, m, 8);                 // full-width scatter complete

    int kb   = k * NB;
    int off  = kb + NB;
    int coff = kb + 2 * NB;
    int Wr = N - off;
    int Wc = N - coff;
    float* A = g_lu + (size_t)m * NN;
    int r0 = (t / nx) * 128, c0 = (t % nx) * 128;
    int tid = threadIdx.x;

    for (int i = tid; i < NB * NB; i += 512) {
        int r = i / NB, c = i % NB;
        sm->r.D[r][c] = A[(size_t)(kb + r) * N + kb + c];
    }
    for (int i = tid; i < 128 * NB; i += 512) {
        int r = i / NB, j = i % NB;
        sm->r.sL[r][j] = (r0 + r < Wr) ? A[(size_t)(off + r0 + r) * N + kb + j] : 0.0f;
    }
    for (int i = tid; i < NB * 128; i += 512) {
        int r = i / 128, c = i % 128;
        int col = c0 + c;
        sm->r.sU[r][c] = (col < Wc) ? A[(size_t)(kb + r) * N + coff + col] : 0.0f;
    }
    __syncthreads();

    if (tid < 128) {
        float v[NB];
        #pragma unroll
        for (int i = 0; i < NB; i++) v[i] = sm->r.sU[i][tid];
        #pragma unroll 1
        for (int j = 0; j < NB; j++) {
            float vj = v[j];
            #pragma unroll
            for (int i = 0; i < NB; i++)
                if (i > j) v[i] -= sm->r.D[i][j] * vj;
        }
        #pragma unroll
        for (int i = 0; i < NB; i++) sm->r.sU[i][tid] = v[i];
    }
    __syncthreads();

    int tx = tid & 15, ty = tid >> 4;
    float acc[4][8] = {};
    #pragma unroll
    for (int j = 0; j < NB; j++) {
        float4 b0 = *(const float4*)&sm->r.sU[j][tx * 4];
        float4 b1 = *(const float4*)&sm->r.sU[j][64 + tx * 4];
        float b[8] = {b0.x, b0.y, b0.z, b0.w, b1.x, b1.y, b1.z, b1.w};
        float a[4];
        #pragma unroll
        for (int i = 0; i < 4; i++) a[i] = sm->r.sL[ty * 4 + i][j];
        #pragma unroll
        for (int i = 0; i < 4; i++)
            #pragma unroll
            for (int l = 0; l < 8; l++) acc[i][l] += a[i] * b[l];
    }
    #pragma unroll
    for (int i = 0; i < 4; i++) {
        int row = r0 + ty * 4 + i;
        if (row >= Wr) continue;
        float* orow = A + (size_t)(off + row) * N + coff;
        #pragma unroll
        for (int l = 0; l < 8; l++) {
            int col = c0 + ((l < 4) ? (tx * 4 + l) : (64 + tx * 4 + l - 4));
            if (col < Wc) orow[col] -= acc[i][l];
        }
    }
}

// grid x = matrix; grid y: 0 gatherN | 1-8 gatherF | 9 scatterN | 10-17 scatterF
//                         | 18 panel(kp) | 19.. rest tiles (kr)
__global__ void __launch_bounds__(512) fused_step(int kp, int kr, int nx) {
    __shared__ SmemU sm;
    int m = blockIdx.x, y = blockIdx.y;
    if (y < 18) {
        if (kr < 0) return;
        if (y == 0) gatherN_role(kr, m);
        else if (y < 9) gatherF_role(kr, m, y - 1);
        else if (y == 9) scatterN_role(kr, m);
        else scatterF_role(kr, m, y - 10);
    } else if (y == 18) {
        panel_role(&sm, kp, kr, m);
    } else {
        rest_role(&sm, kr, m, y - 19, nx);
    }
}

// ---------------- stage C: scores, top-k, fused weights, bool output ----------------
__global__ void head_kernel(const unsigned char* __restrict__ flags,
                            const float* __restrict__ w1, const float* __restrict__ b1,
                            const float* __restrict__ w2, const float* __restrict__ b2,
                            float* __restrict__ out, int out_size) {
    if (blockIdx.x != 0 || threadIdx.x != 0) return;

    int f[16];
    bool any_off4 = false;
    for (int i = 0; i < 16; i++)
        if ((i & 3) && flags[i]) any_off4 = true;
    if (any_off4) {
        for (int i = 0; i < 16; i++) f[i] = flags[i] ? 1 : 0;
    } else {
        const int* fi = (const int*)flags;
        for (int i = 0; i < 16; i++) f[i] = fi[i] ? 1 : 0;
    }

    int sum = 0;
    for (int i = 0; i < 16; i++) sum += f[i];
    int active = (sum >= 4) ? 1 : 0;

    float neg_inf = __int_as_float(0xff800000);
    float sc[16];
    for (int i = 0; i < 16; i++) sc[i] = f[i] ? g_logdet[i] : neg_inf;

    int used[16] = {};
    for (int t = 0; t < 8; t++) {
        int best = -1;
        float bv = neg_inf;
        for (int i = 0; i < 16; i++) {
            if (used[i]) continue;
            if (best < 0 || sc[i] > bv) { best = i; bv = sc[i]; }
        }
        used[best] = 1;
        g_hdr.idx[t] = best;
    }

    for (int c = 0; c < 10; c++) {
        float a = 0.0f;
        for (int h = 0; h < 32; h++) a += w2[h] * w1[h * 10 + c];
        g_hdr.weff[c] = a;
    }
    float be = b2[0];
    for (int h = 0; h < 32; h++) be += w2[h] * b1[h];
    g_hdr.beff = be;
    g_hdr.active = active;

    for (int i = NN; i < out_size; i++) out[i] = active ? 1.0f : 0.0f;
}

// ---------------- final: fused 3-GEMM (B combined on the fly) + preserve + bias ----
#define SA(p,r,j) sA[((p) * 128 + (r)) * 33 + (j)]
#define SB(p,j,c) sB[((p) * NB + (j)) * 68 + (c)]
__global__ void __launch_bounds__(256) final_kernel(const float* __restrict__ x,
                                                    float* __restrict__ out, int out_size) {
    extern __shared__ float sm[];
    float* sA = sm;                         // 3 * 128 * 33
    float* sB = sm + 3 * 128 * 33;          // 3 * NB * 68

    int r0 = blockIdx.y * 128, c0 = blockIdx.x * 64;
    int tid = threadIdx.x, tx = tid & 15, ty = tid >> 4;

    if (!g_hdr.active) {
        #pragma unroll
        for (int i = 0; i < 8; i++) {
            int row = r0 + ty * 8 + i;
            #pragma unroll
            for (int l = 0; l < 4; l++) {
                int p = row * N + c0 + tx * 4 + l;
                if (p < out_size) out[p] = 0.0f;
            }
        }
        return;
    }

    const float* L[3] = { x + (size_t)g_hdr.idx[0] * NN,
                          x + (size_t)g_hdr.idx[1] * NN,
                          x + (size_t)g_hdr.idx[2] * NN };
    const float* X1 = x + (size_t)g_hdr.idx[1] * NN;
    const float* X2 = x + (size_t)g_hdr.idx[2] * NN;
    const float* X3 = x + (size_t)g_hdr.idx[3] * NN;
    float w0 = g_hdr.weff[0], w1v = g_hdr.weff[1], w2v = g_hdr.weff[2];
    float w3 = g_hdr.weff[3], w4 = g_hdr.weff[4], w5 = g_hdr.weff[5];

    float acc[8][4] = {};
    for (int kc = 0; kc < N; kc += NB) {
        #pragma unroll
        for (int p = 0; p < 3; p++) {
            for (int i = tid; i < 128 * NB; i += 256) {
                int r = i / NB, j = i % NB;
                SA(p, r, j) = L[p][(size_t)(r0 + r) * N + kc + j];
            }
        }
        for (int i = tid; i < NB * 64; i += 256) {
            int j = i / 64, c = i % 64;
            size_t o = (size_t)(kc + j) * N + c0 + c;
            float t1 = X1[o], t2 = X2[o], t3 = X3[o];
            SB(0, j, c) = w0 * t1 + w1v * t2 + w2v * t3;
            SB(1, j, c) = w3 * t2 + w4 * t3;
            SB(2, j, c) = w5 * t3;
        }
        __syncthreads();
        #pragma unroll 4
        for (int jj = 0; jj < NB; jj++) {
            #pragma unroll
            for (int p = 0; p < 3; p++) {
                float4 bv = *(const float4*)&SB(p, jj, tx * 4);
                float b[4] = {bv.x, bv.y, bv.z, bv.w};
                float a[8];
                #pragma unroll
                for (int i = 0; i < 8; i++) a[i] = SA(p, ty * 8 + i, jj);
                #pragma unroll
                for (int i = 0; i < 8; i++)
                    #pragma unroll
                    for (int l = 0; l < 4; l++) acc[i][l] += a[i] * b[l];
            }
        }
        __syncthreads();
    }

    const float* P0 = x + (size_t)g_hdr.idx[4] * NN;
    const float* P1 = x + (size_t)g_hdr.idx[5] * NN;
    const float* P2 = x + (size_t)g_hdr.idx[6] * NN;
    const float* P3 = x + (size_t)g_hdr.idx[7] * NN;
    float w6 = g_hdr.weff[6], w7 = g_hdr.weff[7], w8 = g_hdr.weff[8], w9 = g_hdr.weff[9];
    float be = g_hdr.beff;

    #pragma unroll
    for (int i = 0; i < 8; i++) {
        int row = r0 + ty * 8 + i;
        #pragma unroll
        for (int l = 0; l < 4; l++) {
            int col = c0 + tx * 4 + l;
            int p = row * N + col;
            float v = acc[i][l] + w6 * P0[p] + w7 * P1[p] + w8 * P2[p] + w9 * P3[p] + be;
            if (p < out_size) out[p] = v;
        }
    }
}

// ---------------- host launcher: single stream, one launch per LU step ----------------
extern "C" void kernel_launch(void* const* d_in, const int* in_sizes, int n_in,
                              void* d_out, int out_size) {
    const float*         x     = (const float*)d_in[0];
    const unsigned char* flags = (const unsigned char*)d_in[1];
    const float*         w1    = (const float*)d_in[2];
    const float*         b1    = (const float*)d_in[3];
    const float*         w2    = (const float*)d_in[4];
    const float*         b2    = (const float*)d_in[5];
    float*               out   = (float*)d_out;

    int fin_smem = (3 * 128 * 33 + 3 * NB * 68) * (int)sizeof(float);
    cudaFuncSetAttribute(final_kernel, cudaFuncAttributeMaxDynamicSharedMemorySize, fin_smem);

    copy_kernel<<<(BATCH * NN / 4 + 255) / 256, 256>>>(x);

    // initial panel: kp=0, no swaps/rest
    fused_step<<<dim3(16, 19), 512>>>(0, -1, 1);

    for (int k = 0; k < NSTEP - 1; k++) {
        int Wr = N - (k + 1) * NB;
        int Wc = N - (k + 2) * NB;
        int nx = (Wc > 0) ? (Wc + 127) / 128 : 0;
        int ny = (Wr + 127) / 128;
        int ntiles = (Wc > 0) ? nx * ny : 0;
        fused_step<<<dim3(16, 19 + ntiles), 512>>>(k + 1, k, (nx > 0) ? nx : 1);
    }

    head_kernel<<<1, 1>>>(flags, w1, b1, w2, b2, out, out_size);
    final_kernel<<<dim3(16, 8), 256, fin_smem>>>(x, out, out_size);
}